// round 11
// baseline (speedup 1.0000x reference)
#include <cuda_runtime.h>
#include <cuda_bf16.h>
#include <math.h>
#include <stdint.h>

#define NNODES 50000
#define NEDGES 800000
#define HID    128
#define NLAYERS 3
#define NGRAPHS 256
#define BN_EPS 1e-5f

// ---------------- scratch ----------------
__device__ float g_h[NNODES * HID];
__device__ float g_t[NNODES * HID];
__device__ float g_s[NNODES * HID];
__device__ float g_gi[NNODES * 3 * HID];
__device__ float g_gh[NNODES * 3 * HID];
__device__ float g_degf[NNODES];
__device__ int   g_degi[NNODES];
__device__ int   g_cursor[NNODES];
__device__ int   g_rs[NNODES + 1];         // CSR row starts (by dst)
__device__ int   g_csr[NEDGES];            // edge ids grouped by dst
__device__ int   g_offs[NGRAPHS + 1];
__device__ float g_z[NGRAPHS * 2 * HID];
__device__ float g_bc[NLAYERS * 384];
// bf16 hi/lo weights [n][k=128]:
// rows 0..127: lin ; layer l: 128+l*512 = [w1h(128); whh(384)] ; wc: 1664+l*384
#define WROWS 2816
__device__ __nv_bfloat16 g_wh[WROWS * 128];
__device__ __nv_bfloat16 g_wl[WROWS * 128];

__device__ __forceinline__ uint32_t smem_u32(const void* p) {
    uint32_t a;
    asm("{ .reg .u64 t; cvta.to.shared.u64 t, %1; cvt.u32.u64 %0, t; }"
        : "=r"(a) : "l"(p));
    return a;
}
__device__ __forceinline__ uint32_t pkbf(__nv_bfloat16 a, __nv_bfloat16 b) {
    __nv_bfloat162 t; t.x = a; t.y = b;
    return *(uint32_t*)&t;
}

#define SW_ADDR(row, c) (((row) << 8) + ((((c) ^ ((row) & 7))) << 4))

#define LDMX4(r0, r1, r2, r3, ad)                                            \
    asm volatile("ldmatrix.sync.aligned.m8n8.x4.shared.b16 {%0,%1,%2,%3}, [%4];" \
                 : "=r"(r0), "=r"(r1), "=r"(r2), "=r"(r3) : "r"(ad))

#define MMA16816(d, a, b)                                                    \
    asm volatile("mma.sync.aligned.m16n8k16.row.col.f32.bf16.bf16.f32 "      \
                 "{%0,%1,%2,%3}, {%4,%5,%6,%7}, {%8,%9}, {%0,%1,%2,%3};"     \
                 : "+f"((d)[0]), "+f"((d)[1]), "+f"((d)[2]), "+f"((d)[3])    \
                 : "r"((a)[0]), "r"((a)[1]), "r"((a)[2]), "r"((a)[3]),       \
                   "r"((b)[0]), "r"((b)[1]))

// ---------------- fused weight prep ----------------
__global__ void wprep(const float* __restrict__ lin_w, const float* __restrict__ msg_w1,
                      const float* __restrict__ whh,
                      __nv_bfloat16* __restrict__ oh, __nv_bfloat16* __restrict__ ol)
{
    const int idx = blockIdx.x * 256 + threadIdx.x;
    if (idx >= 16384 + NLAYERS * 65536) return;
    float v;
    int outrow, k;
    if (idx < 16384) {
        const int n = idx >> 7; k = idx & 127;
        v = lin_w[(size_t)k * 128 + n];
        outrow = n;
    } else {
        const int idx2 = idx - 16384;
        const int l = idx2 / 65536;
        const int r = idx2 % 65536;
        if (r < 16384) {
            const int n = r >> 7; k = r & 127;
            v = msg_w1[(size_t)l * 144 * 128 + (size_t)k * 128 + n];
            outrow = 128 + l * 512 + n;
        } else {
            const int r2 = r - 16384;
            const int n = r2 >> 7; k = r2 & 127;
            v = whh[(size_t)l * 49152 + r2];
            outrow = 128 + l * 512 + 128 + n;
        }
    }
    const __nv_bfloat16 h = __float2bfloat16_rn(v);
    const size_t o = (size_t)outrow * 128 + k;
    oh[o] = h;
    ol[o] = __float2bfloat16_rn(v - __bfloat162float(h));
}

// Wc^T[n][j] = sum_o W2[j][o]*wih[n][o]; bc[n] = sum_o b2[o]*wih[n][o]
__global__ void wc_kernel(const float* __restrict__ msg_w2, const float* __restrict__ wih,
                          const float* __restrict__ msg_b2,
                          __nv_bfloat16* __restrict__ oh, __nv_bfloat16* __restrict__ ol,
                          float* __restrict__ bc)
{
    const int l = blockIdx.x / 384;
    const int n = blockIdx.x % 384;
    const int j = threadIdx.x;     // 128
    const float* w2 = msg_w2 + (size_t)l * 128 * 128;
    __shared__ float wr[128];
    __shared__ float red[128];
    wr[j] = wih[(size_t)l * 384 * 128 + (size_t)n * 128 + j];
    __syncthreads();
    float acc = 0.f;
    const float* w2r = w2 + (size_t)j * 128;
#pragma unroll 8
    for (int o = 0; o < 128; ++o) acc += w2r[o] * wr[o];
    const __nv_bfloat16 h = __float2bfloat16_rn(acc);
    const size_t outrow = (size_t)(1664 + l * 384 + n);
    oh[outrow * 128 + j] = h;
    ol[outrow * 128 + j] = __float2bfloat16_rn(acc - __bfloat162float(h));
    red[j] = msg_b2[l * 128 + j] * wr[j];
    __syncthreads();
    for (int st = 64; st > 0; st >>= 1) {
        if (j < st) red[j] += red[j + st];
        __syncthreads();
    }
    if (j == 0) bc[l * 384 + n] = red[0];
}

// ---------------- CSR build ----------------
__global__ void hist_kernel(const int* __restrict__ ei, int* __restrict__ degi)
{
    const int e = blockIdx.x * blockDim.x + threadIdx.x;
    if (e < NEDGES) atomicAdd(&degi[__ldg(ei + NEDGES + e)], 1);
}

// exclusive scan of degi[0..NNODES) -> rs, one block of 1024 threads
#define SCAN_CH 49
__global__ void scan_kernel(const int* __restrict__ degi, int* __restrict__ rs)
{
    const int tid = threadIdx.x;   // 1024
    __shared__ int sums[1024];
    const int base = tid * SCAN_CH;
    int local = 0;
#pragma unroll
    for (int i = 0; i < SCAN_CH; ++i) {
        const int idx = base + i;
        local += (idx < NNODES) ? degi[idx] : 0;
    }
    sums[tid] = local;
    __syncthreads();
    // inclusive Hillis-Steele scan
    for (int off = 1; off < 1024; off <<= 1) {
        int v = (tid >= off) ? sums[tid - off] : 0;
        __syncthreads();
        sums[tid] += v;
        __syncthreads();
    }
    int run = sums[tid] - local;   // exclusive offset for this thread's chunk
#pragma unroll
    for (int i = 0; i < SCAN_CH; ++i) {
        const int idx = base + i;
        if (idx < NNODES) {
            rs[idx] = run;
            run += degi[idx];
        }
    }
    if (tid == 1023) rs[NNODES] = sums[1023];
}

__global__ void scatter_kernel(const int* __restrict__ ei, const int* __restrict__ rs,
                               int* __restrict__ cursor, int* __restrict__ csr)
{
    const int e = blockIdx.x * blockDim.x + threadIdx.x;
    if (e >= NEDGES) return;
    const int dst = __ldg(ei + NEDGES + e);
    const int pos = rs[dst] + atomicAdd(&cursor[dst], 1);
    csr[pos] = e;
}

// ---------------- bf16-split tensor-core GEMM (R9 structure) ----------------
#define MG_SMEM 98304

__global__ void __launch_bounds__(256, 2)
mma_gemm(const float* __restrict__ A, const __nv_bfloat16* __restrict__ Bh,
         const __nv_bfloat16* __restrict__ Bl, float* __restrict__ C1, int ldc1,
         float* __restrict__ C2, int M, const float* __restrict__ bias1,
         const float* __restrict__ bias2, const float* __restrict__ rowScale,
         int doRelu)
{
    extern __shared__ char sm[];
    const int tid = threadIdx.x;
    const int m0 = blockIdx.x * 64;
    const int n0 = blockIdx.y * 128;

#pragma unroll
    for (int p = 0; p < 4; ++p) {
        const int idx = tid + p * 256;
        const int m = idx >> 4, c = idx & 15;
        const int gm = m0 + m;
        float4 v0 = make_float4(0.f, 0.f, 0.f, 0.f), v1 = v0;
        if (gm < M) {
            v0 = *(const float4*)(A + (size_t)gm * 128 + c * 8);
            v1 = *(const float4*)(A + (size_t)gm * 128 + c * 8 + 4);
        }
        const float f[8] = {v0.x, v0.y, v0.z, v0.w, v1.x, v1.y, v1.z, v1.w};
        __nv_bfloat16 h[8], l[8];
#pragma unroll
        for (int j = 0; j < 8; ++j) {
            h[j] = __float2bfloat16_rn(f[j]);
            l[j] = __float2bfloat16_rn(f[j] - __bfloat162float(h[j]));
        }
        uint4 hv, lv;
        hv.x = pkbf(h[0], h[1]); hv.y = pkbf(h[2], h[3]);
        hv.z = pkbf(h[4], h[5]); hv.w = pkbf(h[6], h[7]);
        lv.x = pkbf(l[0], l[1]); lv.y = pkbf(l[2], l[3]);
        lv.z = pkbf(l[4], l[5]); lv.w = pkbf(l[6], l[7]);
        const int a = SW_ADDR(m, c);
        *(uint4*)(sm + a)         = hv;
        *(uint4*)(sm + 16384 + a) = lv;
    }
#pragma unroll
    for (int p = 0; p < 16; ++p) {
        const int idx = tid + p * 256;
        const int half = idx >> 11;
        const int r = (idx >> 4) & 127, c = idx & 15;
        const __nv_bfloat16* src = half ? Bl : Bh;
        const uint4 v = *(const uint4*)(src + (size_t)(n0 + r) * 128 + c * 8);
        *(uint4*)(sm + (half ? 65536 : 32768) + SW_ADDR(r, c)) = v;
    }
    __syncthreads();

    const int wid = tid >> 5, L = tid & 31;
    const int wm = (wid & 1) * 32;
    const int wn = (wid >> 1) * 32;
    const uint32_t smb = smem_u32(sm);

    float acc[2][4][4];
#pragma unroll
    for (int i = 0; i < 2; ++i)
#pragma unroll
        for (int j = 0; j < 4; ++j)
#pragma unroll
            for (int q = 0; q < 4; ++q) acc[i][j][q] = 0.f;

    const int arow = wm + (L & 15);
    const int acs  = L >> 4;
    const int brow = wn + (L & 7) + ((L & 16) ? 8 : 0);
    const int bcs  = (L >> 3) & 1;

#pragma unroll
    for (int ks = 0; ks < 8; ++ks) {
        const int c0 = ks * 2;
        uint32_t Ah[2][4], Al[2][4];
#pragma unroll
        for (int mf = 0; mf < 2; ++mf) {
            const uint32_t off = SW_ADDR(arow + mf * 16, c0 + acs);
            LDMX4(Ah[mf][0], Ah[mf][1], Ah[mf][2], Ah[mf][3], smb + off);
            LDMX4(Al[mf][0], Al[mf][1], Al[mf][2], Al[mf][3], smb + 16384 + off);
        }
        uint32_t Bhf[4][2], Blf[4][2];
#pragma unroll
        for (int nf = 0; nf < 2; ++nf) {
            const uint32_t off = SW_ADDR(brow + nf * 16, c0 + bcs);
            LDMX4(Bhf[nf * 2][0], Bhf[nf * 2][1], Bhf[nf * 2 + 1][0],
                  Bhf[nf * 2 + 1][1], smb + 32768 + off);
            LDMX4(Blf[nf * 2][0], Blf[nf * 2][1], Blf[nf * 2 + 1][0],
                  Blf[nf * 2 + 1][1], smb + 65536 + off);
        }
#pragma unroll
        for (int mf = 0; mf < 2; ++mf)
#pragma unroll
            for (int j = 0; j < 4; ++j) {
                MMA16816(acc[mf][j], Ah[mf], Bhf[j]);
                MMA16816(acc[mf][j], Ah[mf], Blf[j]);
                MMA16816(acc[mf][j], Al[mf], Bhf[j]);
            }
    }

#pragma unroll
    for (int mf = 0; mf < 2; ++mf) {
        const int rbase = m0 + wm + mf * 16 + (L >> 2);
#pragma unroll
        for (int half = 0; half < 2; ++half) {
            const int r = rbase + half * 8;
            if (r >= M) continue;
            const float rs = rowScale ? __ldg(rowScale + r) : 0.f;
#pragma unroll
            for (int j = 0; j < 4; ++j) {
                const int col = n0 + wn + j * 8 + 2 * (L & 3);
                float o0, o1;
                if (!C2) {
                    o0 = acc[mf][j][half * 2]     + __ldg(bias1 + col);
                    o1 = acc[mf][j][half * 2 + 1] + __ldg(bias1 + col + 1);
                    if (rowScale) {
                        o0 += __ldg(bias2 + col)     * rs;
                        o1 += __ldg(bias2 + col + 1) * rs;
                    }
                    if (doRelu) { o0 = fmaxf(o0, 0.f); o1 = fmaxf(o1, 0.f); }
                    *(float2*)(C1 + (size_t)r * ldc1 + col) = make_float2(o0, o1);
                } else if (col < 128) {
                    o0 = acc[mf][j][half * 2]     + __ldg(bias1 + col);
                    o1 = acc[mf][j][half * 2 + 1] + __ldg(bias1 + col + 1);
                    *(float2*)(C1 + (size_t)r * ldc1 + col) = make_float2(o0, o1);
                } else {
                    const int c2 = col - 128;
                    o0 = acc[mf][j][half * 2]     + __ldg(bias2 + c2);
                    o1 = acc[mf][j][half * 2 + 1] + __ldg(bias2 + c2 + 1);
                    *(float2*)(C2 + (size_t)r * 384 + c2) = make_float2(o0, o1);
                }
            }
        }
    }
}

// ---------------- CSR edge aggregation (gather, no atomics) ----------------
// warp handles nodes in grid-stride; per edge: m = relu(t[src] + ea@W1e); acc += m
__global__ void __launch_bounds__(256)
edge_agg_kernel(const int* __restrict__ ei, const float* __restrict__ ea,
                const int* __restrict__ csr, const int* __restrict__ rs,
                const float* __restrict__ t, float* __restrict__ s,
                float* __restrict__ degf, const float* __restrict__ w1e)
{
    const int lane = threadIdx.x & 31;
    float4 w[16];
#pragma unroll
    for (int j = 0; j < 16; ++j)
        w[j] = *(const float4*)(w1e + j * 128 + lane * 4);

    const int warp = blockIdx.x * (blockDim.x >> 5) + (threadIdx.x >> 5);
    const int nw = gridDim.x * (blockDim.x >> 5);
    for (int node = warp; node < NNODES; node += nw) {
        const int start = __ldg(rs + node), end = __ldg(rs + node + 1);
        float4 acc = make_float4(0.f, 0.f, 0.f, 0.f);
        for (int p = start; p < end; ++p) {
            const int e = __ldg(csr + p);
            const int src = __ldg(ei + e);
            float4 m = *(const float4*)(t + (size_t)src * 128 + lane * 4);
            const float4* ev = (const float4*)(ea + (size_t)e * 16);
#pragma unroll
            for (int q = 0; q < 4; ++q) {
                const float4 e4 = __ldg(ev + q);
                const float4 w0 = w[q * 4 + 0], w1 = w[q * 4 + 1];
                const float4 w2 = w[q * 4 + 2], w3 = w[q * 4 + 3];
                m.x += e4.x * w0.x + e4.y * w1.x + e4.z * w2.x + e4.w * w3.x;
                m.y += e4.x * w0.y + e4.y * w1.y + e4.z * w2.y + e4.w * w3.y;
                m.z += e4.x * w0.z + e4.y * w1.z + e4.z * w2.z + e4.w * w3.z;
                m.w += e4.x * w0.w + e4.y * w1.w + e4.z * w2.w + e4.w * w3.w;
            }
            acc.x += fmaxf(m.x, 0.f);
            acc.y += fmaxf(m.y, 0.f);
            acc.z += fmaxf(m.z, 0.f);
            acc.w += fmaxf(m.w, 0.f);
        }
        if (lane == 0) degf[node] = (float)(end - start);
        *(float4*)(s + (size_t)node * 128 + lane * 4) = acc;
    }
}

// ---------------- fused GRU + BN + residual ----------------
__device__ __forceinline__ float gru1(float ir, float iz, float in_, float hr,
                                      float hz, float hn, float h,
                                      float ga, float be, float mu, float va)
{
    const float r = 1.f / (1.f + expf(-(ir + hr)));
    const float z = 1.f / (1.f + expf(-(iz + hz)));
    const float n = tanhf(in_ + r * hn);
    const float hnew = (1.f - z) * n + z * h;
    const float bn = (hnew - mu) * rsqrtf(va + BN_EPS) * ga + be;
    return h + bn;
}

__global__ void gru_bn_kernel(const float* __restrict__ gi, const float* __restrict__ gh,
                              float* __restrict__ h,
                              const float* __restrict__ gamma, const float* __restrict__ beta,
                              const float* __restrict__ mean,  const float* __restrict__ var)
{
    const int idx = blockIdx.x * blockDim.x + threadIdx.x;
    if (idx >= NNODES * 32) return;
    const int m = idx >> 5;
    const int c = idx & 31;
    const size_t gb = (size_t)m * 384 + c * 4;
    const float4 ir = *(const float4*)(gi + gb);
    const float4 iz = *(const float4*)(gi + gb + 128);
    const float4 in_ = *(const float4*)(gi + gb + 256);
    const float4 hr = *(const float4*)(gh + gb);
    const float4 hz = *(const float4*)(gh + gb + 128);
    const float4 hn = *(const float4*)(gh + gb + 256);
    float4 hv = *(float4*)(h + (size_t)m * 128 + c * 4);
    const float4 ga = *(const float4*)(gamma + c * 4);
    const float4 be = *(const float4*)(beta + c * 4);
    const float4 mu = *(const float4*)(mean + c * 4);
    const float4 va = *(const float4*)(var + c * 4);
    hv.x = gru1(ir.x, iz.x, in_.x, hr.x, hz.x, hn.x, hv.x, ga.x, be.x, mu.x, va.x);
    hv.y = gru1(ir.y, iz.y, in_.y, hr.y, hz.y, hn.y, hv.y, ga.y, be.y, mu.y, va.y);
    hv.z = gru1(ir.z, iz.z, in_.z, hr.z, hz.z, hn.z, hv.z, ga.z, be.z, mu.z, va.z);
    hv.w = gru1(ir.w, iz.w, in_.w, hr.w, hz.w, hn.w, hv.w, ga.w, be.w, mu.w, va.w);
    *(float4*)(h + (size_t)m * 128 + c * 4) = hv;
}

__global__ void offsets_kernel(const int* __restrict__ batch, int* __restrict__ offs)
{
    const int g = blockIdx.x * blockDim.x + threadIdx.x;
    if (g > NGRAPHS) return;
    int lo = 0, hi = NNODES;
    while (lo < hi) {
        const int mid = (lo + hi) >> 1;
        if (batch[mid] < g) lo = mid + 1; else hi = mid;
    }
    offs[g] = lo;
}

__global__ void readout_kernel(const float* __restrict__ h, const int* __restrict__ offs,
                               float* __restrict__ z)
{
    const int g = blockIdx.x;
    const int d = threadIdx.x;
    const int s0 = offs[g], e0 = offs[g + 1];
    float sum = 0.f, mx = -INFINITY;
    for (int r = s0; r < e0; ++r) {
        const float v = h[(size_t)r * 128 + d];
        sum += v;
        mx = fmaxf(mx, v);
    }
    const int cnt = e0 - s0;
    float mean = sum / fmaxf((float)cnt, 1.f);
    if (cnt == 0) { mean = 0.f; mx = 0.f; }
    z[g * 256 + d] = mean;
    z[g * 256 + 128 + d] = mx;
}

__global__ void ro_kernel(const float* __restrict__ z, const float* __restrict__ w,
                          const float* __restrict__ b, float* __restrict__ out)
{
    const int g = blockIdx.x;
    const int n = threadIdx.x;
    __shared__ float zs[256];
    zs[n] = z[g * 256 + n];
    zs[n + 128] = z[g * 256 + 128 + n];
    __syncthreads();
    float acc = b[n];
#pragma unroll 8
    for (int k = 0; k < 256; ++k)
        acc += zs[k] * w[k * 128 + n];
    out[g * 128 + n] = fmaxf(acc, 0.f);
}

// ---------------- host ----------------
extern "C" void kernel_launch(void* const* d_in, const int* in_sizes, int n_in,
                              void* d_out, int out_size)
{
    const float* x     = (const float*)d_in[0];
    const int*   ei    = (const int*)d_in[1];
    const float* ea    = (const float*)d_in[2];
    const int*   batch = (const int*)d_in[3];
    const int base = (n_in >= 21) ? 5 : 4;
    const float* lin_w  = (const float*)d_in[base + 0];
    const float* lin_b  = (const float*)d_in[base + 1];
    const float* msg_w1 = (const float*)d_in[base + 2];
    const float* msg_b1 = (const float*)d_in[base + 3];
    const float* msg_w2 = (const float*)d_in[base + 4];
    const float* msg_b2 = (const float*)d_in[base + 5];
    const float* bn_g   = (const float*)d_in[base + 6];
    const float* bn_b   = (const float*)d_in[base + 7];
    const float* bn_m   = (const float*)d_in[base + 8];
    const float* bn_v   = (const float*)d_in[base + 9];
    const float* wih    = (const float*)d_in[base + 10];
    const float* whh    = (const float*)d_in[base + 11];
    const float* bih    = (const float*)d_in[base + 12];
    const float* bhh    = (const float*)d_in[base + 13];
    const float* ro_w   = (const float*)d_in[base + 14];
    const float* ro_b   = (const float*)d_in[base + 15];
    float* out = (float*)d_out;

    float *h, *t, *s, *gi, *gh, *degf, *z, *bc;
    int *degi, *cursor, *rs, *csr, *offs;
    __nv_bfloat16 *wh_, *wl_;
    cudaGetSymbolAddress((void**)&h,    g_h);
    cudaGetSymbolAddress((void**)&t,    g_t);
    cudaGetSymbolAddress((void**)&s,    g_s);
    cudaGetSymbolAddress((void**)&gi,   g_gi);
    cudaGetSymbolAddress((void**)&gh,   g_gh);
    cudaGetSymbolAddress((void**)&degf, g_degf);
    cudaGetSymbolAddress((void**)&degi, g_degi);
    cudaGetSymbolAddress((void**)&cursor, g_cursor);
    cudaGetSymbolAddress((void**)&rs,   g_rs);
    cudaGetSymbolAddress((void**)&csr,  g_csr);
    cudaGetSymbolAddress((void**)&offs, g_offs);
    cudaGetSymbolAddress((void**)&z,    g_z);
    cudaGetSymbolAddress((void**)&bc,   g_bc);
    cudaGetSymbolAddress((void**)&wh_,  g_wh);
    cudaGetSymbolAddress((void**)&wl_,  g_wl);

    cudaFuncSetAttribute(mma_gemm,
                         cudaFuncAttributeMaxDynamicSharedMemorySize, MG_SMEM);

    // weight prep
    wprep<<<(16384 + NLAYERS * 65536 + 255) / 256, 256>>>(lin_w, msg_w1, whh, wh_, wl_);
    wc_kernel<<<NLAYERS * 384, 128>>>(msg_w2, wih, msg_b2, wh_, wl_, bc);

    // CSR build (once per launch)
    cudaMemsetAsync(degi, 0, NNODES * sizeof(int), 0);
    cudaMemsetAsync(cursor, 0, NNODES * sizeof(int), 0);
    hist_kernel<<<(NEDGES + 255) / 256, 256>>>(ei, degi);
    scan_kernel<<<1, 1024>>>(degi, rs);
    scatter_kernel<<<(NEDGES + 255) / 256, 256>>>(ei, rs, cursor, csr);

    const int gx = (NNODES + 63) / 64;

    // h = relu(x @ lin_w + lin_b)
    {
        dim3 grid(gx, 1);
        mma_gemm<<<grid, 256, MG_SMEM>>>(x, wh_, wl_, h, 128, nullptr, NNODES,
                                         lin_b, nullptr, nullptr, 1);
    }

    for (int l = 0; l < NLAYERS; ++l) {
        const float* W1e = msg_w1 + (size_t)l * 144 * 128 + 128 * 128;
        const int wbase = 128 + l * 512;
        const int cbase = 1664 + l * 384;

        // [t | gh] = h @ [w1h; whh]^T
        {
            dim3 grid(gx, 4);
            mma_gemm<<<grid, 256, MG_SMEM>>>(
                h, wh_ + (size_t)wbase * 128, wl_ + (size_t)wbase * 128,
                t, 128, gh, NNODES, msg_b1 + l * 128, bhh + l * 384, nullptr, 0);
        }
        // s = per-dst gather-aggregate (no atomics, no memset)
        edge_agg_kernel<<<1563, 256>>>(ei, ea, csr, rs, t, s, degf, W1e);
        // gi = s @ Wc + bih + deg*bc
        {
            dim3 grid(gx, 3);
            mma_gemm<<<grid, 256, MG_SMEM>>>(
                s, wh_ + (size_t)cbase * 128, wl_ + (size_t)cbase * 128,
                gi, 384, nullptr, NNODES, bih + l * 384, bc + l * 384, degf, 0);
        }
        gru_bn_kernel<<<(NNODES * 32 + 255) / 256, 256>>>(
            gi, gh, h, bn_g + l * 128, bn_b + l * 128, bn_m + l * 128, bn_v + l * 128);
    }

    offsets_kernel<<<2, 256>>>(batch, offs);
    readout_kernel<<<NGRAPHS, 128>>>(h, offs, z);
    ro_kernel<<<NGRAPHS, 128>>>(z, ro_w, ro_b, out);
}

// round 12
// speedup vs baseline: 1.5127x; 1.5127x over previous
#include <cuda_runtime.h>
#include <cuda_bf16.h>
#include <math.h>
#include <stdint.h>

#define NNODES 50000
#define NEDGES 800000
#define HID    128
#define NLAYERS 3
#define NGRAPHS 256
#define BN_EPS 1e-5f

// ---------------- scratch ----------------
__device__ float g_h[NNODES * HID];
__device__ float g_t[NNODES * HID];
__device__ float g_s[NNODES * HID];
__device__ float g_gi[NNODES * 3 * HID];
__device__ float g_gh[NNODES * 3 * HID];
__device__ float g_deg[NNODES];
__device__ int   g_offs[NGRAPHS + 1];
__device__ float g_z[NGRAPHS * 2 * HID];
__device__ float g_bc[NLAYERS * 384];
// bf16 hi/lo weights [n][k=128]:
// rows 0..127: lin ; layer l: 128+l*512 = [w1h(128); whh(384)] ; wc: 1664+l*384
#define WROWS 2816
__device__ __nv_bfloat16 g_wh[WROWS * 128];
__device__ __nv_bfloat16 g_wl[WROWS * 128];

__device__ __forceinline__ uint32_t smem_u32(const void* p) {
    uint32_t a;
    asm("{ .reg .u64 t; cvta.to.shared.u64 t, %1; cvt.u32.u64 %0, t; }"
        : "=r"(a) : "l"(p));
    return a;
}
__device__ __forceinline__ uint32_t pkbf(__nv_bfloat16 a, __nv_bfloat16 b) {
    __nv_bfloat162 t; t.x = a; t.y = b;
    return *(uint32_t*)&t;
}

#define SW_ADDR(row, c) (((row) << 8) + ((((c) ^ ((row) & 7))) << 4))

#define LDMX4(r0, r1, r2, r3, ad)                                            \
    asm volatile("ldmatrix.sync.aligned.m8n8.x4.shared.b16 {%0,%1,%2,%3}, [%4];" \
                 : "=r"(r0), "=r"(r1), "=r"(r2), "=r"(r3) : "r"(ad))

#define MMA16816(d, a, b)                                                    \
    asm volatile("mma.sync.aligned.m16n8k16.row.col.f32.bf16.bf16.f32 "      \
                 "{%0,%1,%2,%3}, {%4,%5,%6,%7}, {%8,%9}, {%0,%1,%2,%3};"     \
                 : "+f"((d)[0]), "+f"((d)[1]), "+f"((d)[2]), "+f"((d)[3])    \
                 : "r"((a)[0]), "r"((a)[1]), "r"((a)[2]), "r"((a)[3]),       \
                   "r"((b)[0]), "r"((b)[1]))

// ---------------- fused weight prep ----------------
__global__ void wprep(const float* __restrict__ lin_w, const float* __restrict__ msg_w1,
                      const float* __restrict__ whh,
                      __nv_bfloat16* __restrict__ oh, __nv_bfloat16* __restrict__ ol)
{
    const int idx = blockIdx.x * 256 + threadIdx.x;
    if (idx >= 16384 + NLAYERS * 65536) return;
    float v;
    int outrow, k;
    if (idx < 16384) {
        const int n = idx >> 7; k = idx & 127;
        v = lin_w[(size_t)k * 128 + n];
        outrow = n;
    } else {
        const int idx2 = idx - 16384;
        const int l = idx2 / 65536;
        const int r = idx2 % 65536;
        if (r < 16384) {
            const int n = r >> 7; k = r & 127;
            v = msg_w1[(size_t)l * 144 * 128 + (size_t)k * 128 + n];
            outrow = 128 + l * 512 + n;
        } else {
            const int r2 = r - 16384;
            const int n = r2 >> 7; k = r2 & 127;
            v = whh[(size_t)l * 49152 + r2];
            outrow = 128 + l * 512 + 128 + n;
        }
    }
    const __nv_bfloat16 h = __float2bfloat16_rn(v);
    const size_t o = (size_t)outrow * 128 + k;
    oh[o] = h;
    ol[o] = __float2bfloat16_rn(v - __bfloat162float(h));
}

// Wc^T[n][j] = sum_o W2[j][o]*wih[n][o]; bc[n] = sum_o b2[o]*wih[n][o]
__global__ void wc_kernel(const float* __restrict__ msg_w2, const float* __restrict__ wih,
                          const float* __restrict__ msg_b2,
                          __nv_bfloat16* __restrict__ oh, __nv_bfloat16* __restrict__ ol,
                          float* __restrict__ bc)
{
    const int l = blockIdx.x / 384;
    const int n = blockIdx.x % 384;
    const int j = threadIdx.x;     // 128
    const float* w2 = msg_w2 + (size_t)l * 128 * 128;
    __shared__ float wr[128];
    __shared__ float red[128];
    wr[j] = wih[(size_t)l * 384 * 128 + (size_t)n * 128 + j];
    __syncthreads();
    float acc = 0.f;
    const float* w2r = w2 + (size_t)j * 128;
#pragma unroll 8
    for (int o = 0; o < 128; ++o) acc += w2r[o] * wr[o];
    const __nv_bfloat16 h = __float2bfloat16_rn(acc);
    const size_t outrow = (size_t)(1664 + l * 384 + n);
    oh[outrow * 128 + j] = h;
    ol[outrow * 128 + j] = __float2bfloat16_rn(acc - __bfloat162float(h));
    red[j] = msg_b2[l * 128 + j] * wr[j];
    __syncthreads();
    for (int st = 64; st > 0; st >>= 1) {
        if (j < st) red[j] += red[j + st];
        __syncthreads();
    }
    if (j == 0) bc[l * 384 + n] = red[0];
}

__global__ void deg_kernel(const int* __restrict__ ei, float* __restrict__ deg)
{
    const int e = blockIdx.x * blockDim.x + threadIdx.x;
    if (e < NEDGES) atomicAdd(&deg[__ldg(ei + NEDGES + e)], 1.f);
}

// ---------------- bf16-split tensor-core GEMM (R9 structure) ----------------
#define MG_SMEM 98304

__global__ void __launch_bounds__(256, 2)
mma_gemm(const float* __restrict__ A, const __nv_bfloat16* __restrict__ Bh,
         const __nv_bfloat16* __restrict__ Bl, float* __restrict__ C1, int ldc1,
         float* __restrict__ C2, int M, const float* __restrict__ bias1,
         const float* __restrict__ bias2, const float* __restrict__ rowScale,
         int doRelu)
{
    extern __shared__ char sm[];
    const int tid = threadIdx.x;
    const int m0 = blockIdx.x * 64;
    const int n0 = blockIdx.y * 128;

#pragma unroll
    for (int p = 0; p < 4; ++p) {
        const int idx = tid + p * 256;
        const int m = idx >> 4, c = idx & 15;
        const int gm = m0 + m;
        float4 v0 = make_float4(0.f, 0.f, 0.f, 0.f), v1 = v0;
        if (gm < M) {
            v0 = *(const float4*)(A + (size_t)gm * 128 + c * 8);
            v1 = *(const float4*)(A + (size_t)gm * 128 + c * 8 + 4);
        }
        const float f[8] = {v0.x, v0.y, v0.z, v0.w, v1.x, v1.y, v1.z, v1.w};
        __nv_bfloat16 h[8], l[8];
#pragma unroll
        for (int j = 0; j < 8; ++j) {
            h[j] = __float2bfloat16_rn(f[j]);
            l[j] = __float2bfloat16_rn(f[j] - __bfloat162float(h[j]));
        }
        uint4 hv, lv;
        hv.x = pkbf(h[0], h[1]); hv.y = pkbf(h[2], h[3]);
        hv.z = pkbf(h[4], h[5]); hv.w = pkbf(h[6], h[7]);
        lv.x = pkbf(l[0], l[1]); lv.y = pkbf(l[2], l[3]);
        lv.z = pkbf(l[4], l[5]); lv.w = pkbf(l[6], l[7]);
        const int a = SW_ADDR(m, c);
        *(uint4*)(sm + a)         = hv;
        *(uint4*)(sm + 16384 + a) = lv;
    }
#pragma unroll
    for (int p = 0; p < 16; ++p) {
        const int idx = tid + p * 256;
        const int half = idx >> 11;
        const int r = (idx >> 4) & 127, c = idx & 15;
        const __nv_bfloat16* src = half ? Bl : Bh;
        const uint4 v = *(const uint4*)(src + (size_t)(n0 + r) * 128 + c * 8);
        *(uint4*)(sm + (half ? 65536 : 32768) + SW_ADDR(r, c)) = v;
    }
    __syncthreads();

    const int wid = tid >> 5, L = tid & 31;
    const int wm = (wid & 1) * 32;
    const int wn = (wid >> 1) * 32;
    const uint32_t smb = smem_u32(sm);

    float acc[2][4][4];
#pragma unroll
    for (int i = 0; i < 2; ++i)
#pragma unroll
        for (int j = 0; j < 4; ++j)
#pragma unroll
            for (int q = 0; q < 4; ++q) acc[i][j][q] = 0.f;

    const int arow = wm + (L & 15);
    const int acs  = L >> 4;
    const int brow = wn + (L & 7) + ((L & 16) ? 8 : 0);
    const int bcs  = (L >> 3) & 1;

#pragma unroll
    for (int ks = 0; ks < 8; ++ks) {
        const int c0 = ks * 2;
        uint32_t Ah[2][4], Al[2][4];
#pragma unroll
        for (int mf = 0; mf < 2; ++mf) {
            const uint32_t off = SW_ADDR(arow + mf * 16, c0 + acs);
            LDMX4(Ah[mf][0], Ah[mf][1], Ah[mf][2], Ah[mf][3], smb + off);
            LDMX4(Al[mf][0], Al[mf][1], Al[mf][2], Al[mf][3], smb + 16384 + off);
        }
        uint32_t Bhf[4][2], Blf[4][2];
#pragma unroll
        for (int nf = 0; nf < 2; ++nf) {
            const uint32_t off = SW_ADDR(brow + nf * 16, c0 + bcs);
            LDMX4(Bhf[nf * 2][0], Bhf[nf * 2][1], Bhf[nf * 2 + 1][0],
                  Bhf[nf * 2 + 1][1], smb + 32768 + off);
            LDMX4(Blf[nf * 2][0], Blf[nf * 2][1], Blf[nf * 2 + 1][0],
                  Blf[nf * 2 + 1][1], smb + 65536 + off);
        }
#pragma unroll
        for (int mf = 0; mf < 2; ++mf)
#pragma unroll
            for (int j = 0; j < 4; ++j) {
                MMA16816(acc[mf][j], Ah[mf], Bhf[j]);
                MMA16816(acc[mf][j], Ah[mf], Blf[j]);
                MMA16816(acc[mf][j], Al[mf], Bhf[j]);
            }
    }

#pragma unroll
    for (int mf = 0; mf < 2; ++mf) {
        const int rbase = m0 + wm + mf * 16 + (L >> 2);
#pragma unroll
        for (int half = 0; half < 2; ++half) {
            const int r = rbase + half * 8;
            if (r >= M) continue;
            const float rs = rowScale ? __ldg(rowScale + r) : 0.f;
#pragma unroll
            for (int j = 0; j < 4; ++j) {
                const int col = n0 + wn + j * 8 + 2 * (L & 3);
                float o0, o1;
                if (!C2) {
                    o0 = acc[mf][j][half * 2]     + __ldg(bias1 + col);
                    o1 = acc[mf][j][half * 2 + 1] + __ldg(bias1 + col + 1);
                    if (rowScale) {
                        o0 += __ldg(bias2 + col)     * rs;
                        o1 += __ldg(bias2 + col + 1) * rs;
                    }
                    if (doRelu) { o0 = fmaxf(o0, 0.f); o1 = fmaxf(o1, 0.f); }
                    *(float2*)(C1 + (size_t)r * ldc1 + col) = make_float2(o0, o1);
                } else if (col < 128) {
                    o0 = acc[mf][j][half * 2]     + __ldg(bias1 + col);
                    o1 = acc[mf][j][half * 2 + 1] + __ldg(bias1 + col + 1);
                    *(float2*)(C1 + (size_t)r * ldc1 + col) = make_float2(o0, o1);
                } else {
                    const int c2 = col - 128;
                    o0 = acc[mf][j][half * 2]     + __ldg(bias2 + c2);
                    o1 = acc[mf][j][half * 2 + 1] + __ldg(bias2 + c2 + 1);
                    *(float2*)(C2 + (size_t)r * 384 + c2) = make_float2(o0, o1);
                }
            }
        }
    }
}

// ---------------- edge kernel: tensor-core eproj + scatter ----------------
// Tile of 64 edges: eproj[64,128] = ea[64,16] @ W1e (bf16 hi/lo 3-pass MMA),
// then warp-per-edge: s[dst] += relu(t[src] + eproj). W1e^T cached in smem.
// smem layout (bytes): W1h@0 (128*48), W1l@6144, Ah@12288 (64*48), Al@15360,
// eproj@18432 (64 rows * 528B) -> total 52224
#define ET_W1H 0
#define ET_W1L 6144
#define ET_AH  12288
#define ET_AL  15360
#define ET_EP  18432
#define ET_SMEM 52224
#define NTILES (NEDGES / 64)

__global__ void __launch_bounds__(256)
edge_mma_kernel(const int* __restrict__ ei, const float* __restrict__ ea,
                const float* __restrict__ t, float* __restrict__ s,
                const float* __restrict__ w1e)
{
    extern __shared__ char sm[];
    const int tid = threadIdx.x;
    const int wid = tid >> 5, L = tid & 31;
    const uint32_t smb = smem_u32(sm);

    // W1e^T -> smem bf16 hi/lo: [n 0..127][k 0..15], row stride 48B.
    // w1e fp32 layout [k][128]
    for (int i = tid; i < 2048; i += 256) {
        const int n = i >> 4, k = i & 15;
        const float v = __ldg(w1e + k * 128 + n);
        const __nv_bfloat16 hb = __float2bfloat16_rn(v);
        *(__nv_bfloat16*)(sm + ET_W1H + n * 48 + k * 2) = hb;
        *(__nv_bfloat16*)(sm + ET_W1L + n * 48 + k * 2) =
            __float2bfloat16_rn(v - __bfloat162float(hb));
    }
    __syncthreads();

    const int mb = wid & 3;              // m-block (16 edges)
    const int nbase = (wid >> 2) * 64;   // n range 0-63 / 64-127
    const uint32_t aoff = (uint32_t)((mb * 16 + (L & 15)) * 48 + (L >> 4) * 16);
    const int eaEdge = tid >> 2;         // phase-1 mapping
    const int eaK = (tid & 3) * 4;

    for (int tile = blockIdx.x; tile < NTILES; tile += gridDim.x) {
        const int e0 = tile * 64;
        // ---- phase 1: ea tile [64][16] -> bf16 hi/lo smem ----
        {
            const float4 v = *(const float4*)(ea + (size_t)e0 * 16 + tid * 4);
            const float f[4] = {v.x, v.y, v.z, v.w};
            __nv_bfloat16 hh[4], ll[4];
#pragma unroll
            for (int j = 0; j < 4; ++j) {
                hh[j] = __float2bfloat16_rn(f[j]);
                ll[j] = __float2bfloat16_rn(f[j] - __bfloat162float(hh[j]));
            }
            const int a = eaEdge * 48 + eaK * 2;
            *(uint32_t*)(sm + ET_AH + a)     = pkbf(hh[0], hh[1]);
            *(uint32_t*)(sm + ET_AH + a + 4) = pkbf(hh[2], hh[3]);
            *(uint32_t*)(sm + ET_AL + a)     = pkbf(ll[0], ll[1]);
            *(uint32_t*)(sm + ET_AL + a + 4) = pkbf(ll[2], ll[3]);
        }
        __syncthreads();

        // ---- phase 2: MMA eproj = ea @ W1e ----
        uint32_t Ah[4], Al[4];
        LDMX4(Ah[0], Ah[1], Ah[2], Ah[3], smb + ET_AH + aoff);
        LDMX4(Al[0], Al[1], Al[2], Al[3], smb + ET_AL + aoff);
        float acc[8][4];
#pragma unroll
        for (int j = 0; j < 8; ++j)
#pragma unroll
            for (int q = 0; q < 4; ++q) acc[j][q] = 0.f;

#pragma unroll
        for (int nf = 0; nf < 4; ++nf) {
            const uint32_t boff = (uint32_t)((nbase + nf * 16 + (L & 7) +
                                  ((L & 16) ? 8 : 0)) * 48 + ((L >> 3) & 1) * 16);
            uint32_t Bh0[2], Bh1[2], Bl0[2], Bl1[2];
            LDMX4(Bh0[0], Bh0[1], Bh1[0], Bh1[1], smb + ET_W1H + boff);
            LDMX4(Bl0[0], Bl0[1], Bl1[0], Bl1[1], smb + ET_W1L + boff);
            MMA16816(acc[nf * 2], Ah, Bh0);
            MMA16816(acc[nf * 2], Ah, Bl0);
            MMA16816(acc[nf * 2], Al, Bh0);
            MMA16816(acc[nf * 2 + 1], Ah, Bh1);
            MMA16816(acc[nf * 2 + 1], Ah, Bl1);
            MMA16816(acc[nf * 2 + 1], Al, Bh1);
        }
        // write eproj fp32 to smem [64][132 floats]
#pragma unroll
        for (int j = 0; j < 8; ++j) {
            const int col = nbase + j * 8 + 2 * (L & 3);
#pragma unroll
            for (int half = 0; half < 2; ++half) {
                const int row = mb * 16 + (L >> 2) + half * 8;
                *(float2*)(sm + ET_EP + row * 528 + col * 4) =
                    make_float2(acc[j][half * 2], acc[j][half * 2 + 1]);
            }
        }
        __syncthreads();

        // ---- phase 3: warp-per-edge scatter ----
#pragma unroll
        for (int i = 0; i < 8; ++i) {
            const int eL = wid * 8 + i;
            const int e = e0 + eL;
            const int src = __ldg(ei + e);
            const int dst = __ldg(ei + NEDGES + e);
            const float4 ep = *(const float4*)(sm + ET_EP + eL * 528 + L * 16);
            const float4 tv = *(const float4*)(t + (size_t)src * 128 + L * 4);
            float4 m;
            m.x = fmaxf(tv.x + ep.x, 0.f);
            m.y = fmaxf(tv.y + ep.y, 0.f);
            m.z = fmaxf(tv.z + ep.z, 0.f);
            m.w = fmaxf(tv.w + ep.w, 0.f);
            float* p = s + (size_t)dst * 128 + L * 4;
            asm volatile("red.global.add.v4.f32 [%0], {%1,%2,%3,%4};"
                         :: "l"(p), "f"(m.x), "f"(m.y), "f"(m.z), "f"(m.w)
                         : "memory");
        }
        __syncthreads();
    }
}

// ---------------- fused GRU + BN + residual ----------------
__device__ __forceinline__ float gru1(float ir, float iz, float in_, float hr,
                                      float hz, float hn, float h,
                                      float ga, float be, float mu, float va)
{
    const float r = 1.f / (1.f + expf(-(ir + hr)));
    const float z = 1.f / (1.f + expf(-(iz + hz)));
    const float n = tanhf(in_ + r * hn);
    const float hnew = (1.f - z) * n + z * h;
    const float bn = (hnew - mu) * rsqrtf(va + BN_EPS) * ga + be;
    return h + bn;
}

__global__ void gru_bn_kernel(const float* __restrict__ gi, const float* __restrict__ gh,
                              float* __restrict__ h,
                              const float* __restrict__ gamma, const float* __restrict__ beta,
                              const float* __restrict__ mean,  const float* __restrict__ var)
{
    const int idx = blockIdx.x * blockDim.x + threadIdx.x;
    if (idx >= NNODES * 32) return;
    const int m = idx >> 5;
    const int c = idx & 31;
    const size_t gb = (size_t)m * 384 + c * 4;
    const float4 ir = *(const float4*)(gi + gb);
    const float4 iz = *(const float4*)(gi + gb + 128);
    const float4 in_ = *(const float4*)(gi + gb + 256);
    const float4 hr = *(const float4*)(gh + gb);
    const float4 hz = *(const float4*)(gh + gb + 128);
    const float4 hn = *(const float4*)(gh + gb + 256);
    float4 hv = *(float4*)(h + (size_t)m * 128 + c * 4);
    const float4 ga = *(const float4*)(gamma + c * 4);
    const float4 be = *(const float4*)(beta + c * 4);
    const float4 mu = *(const float4*)(mean + c * 4);
    const float4 va = *(const float4*)(var + c * 4);
    hv.x = gru1(ir.x, iz.x, in_.x, hr.x, hz.x, hn.x, hv.x, ga.x, be.x, mu.x, va.x);
    hv.y = gru1(ir.y, iz.y, in_.y, hr.y, hz.y, hn.y, hv.y, ga.y, be.y, mu.y, va.y);
    hv.z = gru1(ir.z, iz.z, in_.z, hr.z, hz.z, hn.z, hv.z, ga.z, be.z, mu.z, va.z);
    hv.w = gru1(ir.w, iz.w, in_.w, hr.w, hz.w, hn.w, hv.w, ga.w, be.w, mu.w, va.w);
    *(float4*)(h + (size_t)m * 128 + c * 4) = hv;
}

__global__ void offsets_kernel(const int* __restrict__ batch, int* __restrict__ offs)
{
    const int g = blockIdx.x * blockDim.x + threadIdx.x;
    if (g > NGRAPHS) return;
    int lo = 0, hi = NNODES;
    while (lo < hi) {
        const int mid = (lo + hi) >> 1;
        if (batch[mid] < g) lo = mid + 1; else hi = mid;
    }
    offs[g] = lo;
}

__global__ void readout_kernel(const float* __restrict__ h, const int* __restrict__ offs,
                               float* __restrict__ z)
{
    const int g = blockIdx.x;
    const int d = threadIdx.x;
    const int s0 = offs[g], e0 = offs[g + 1];
    float sum = 0.f, mx = -INFINITY;
    for (int r = s0; r < e0; ++r) {
        const float v = h[(size_t)r * 128 + d];
        sum += v;
        mx = fmaxf(mx, v);
    }
    const int cnt = e0 - s0;
    float mean = sum / fmaxf((float)cnt, 1.f);
    if (cnt == 0) { mean = 0.f; mx = 0.f; }
    z[g * 256 + d] = mean;
    z[g * 256 + 128 + d] = mx;
}

__global__ void ro_kernel(const float* __restrict__ z, const float* __restrict__ w,
                          const float* __restrict__ b, float* __restrict__ out)
{
    const int g = blockIdx.x;
    const int n = threadIdx.x;
    __shared__ float zs[256];
    zs[n] = z[g * 256 + n];
    zs[n + 128] = z[g * 256 + 128 + n];
    __syncthreads();
    float acc = b[n];
#pragma unroll 8
    for (int k = 0; k < 256; ++k)
        acc += zs[k] * w[k * 128 + n];
    out[g * 128 + n] = fmaxf(acc, 0.f);
}

// ---------------- host ----------------
extern "C" void kernel_launch(void* const* d_in, const int* in_sizes, int n_in,
                              void* d_out, int out_size)
{
    const float* x     = (const float*)d_in[0];
    const int*   ei    = (const int*)d_in[1];
    const float* ea    = (const float*)d_in[2];
    const int*   batch = (const int*)d_in[3];
    const int base = (n_in >= 21) ? 5 : 4;
    const float* lin_w  = (const float*)d_in[base + 0];
    const float* lin_b  = (const float*)d_in[base + 1];
    const float* msg_w1 = (const float*)d_in[base + 2];
    const float* msg_b1 = (const float*)d_in[base + 3];
    const float* msg_w2 = (const float*)d_in[base + 4];
    const float* msg_b2 = (const float*)d_in[base + 5];
    const float* bn_g   = (const float*)d_in[base + 6];
    const float* bn_b   = (const float*)d_in[base + 7];
    const float* bn_m   = (const float*)d_in[base + 8];
    const float* bn_v   = (const float*)d_in[base + 9];
    const float* wih    = (const float*)d_in[base + 10];
    const float* whh    = (const float*)d_in[base + 11];
    const float* bih    = (const float*)d_in[base + 12];
    const float* bhh    = (const float*)d_in[base + 13];
    const float* ro_w   = (const float*)d_in[base + 14];
    const float* ro_b   = (const float*)d_in[base + 15];
    float* out = (float*)d_out;

    float *h, *t, *s, *gi, *gh, *deg, *z, *bc;
    int* offs;
    __nv_bfloat16 *wh_, *wl_;
    cudaGetSymbolAddress((void**)&h,   g_h);
    cudaGetSymbolAddress((void**)&t,   g_t);
    cudaGetSymbolAddress((void**)&s,   g_s);
    cudaGetSymbolAddress((void**)&gi,  g_gi);
    cudaGetSymbolAddress((void**)&gh,  g_gh);
    cudaGetSymbolAddress((void**)&deg, g_deg);
    cudaGetSymbolAddress((void**)&offs, g_offs);
    cudaGetSymbolAddress((void**)&z,   g_z);
    cudaGetSymbolAddress((void**)&bc,  g_bc);
    cudaGetSymbolAddress((void**)&wh_, g_wh);
    cudaGetSymbolAddress((void**)&wl_, g_wl);

    cudaFuncSetAttribute(mma_gemm,
                         cudaFuncAttributeMaxDynamicSharedMemorySize, MG_SMEM);
    cudaFuncSetAttribute(edge_mma_kernel,
                         cudaFuncAttributeMaxDynamicSharedMemorySize, ET_SMEM);

    // weight prep
    wprep<<<(16384 + NLAYERS * 65536 + 255) / 256, 256>>>(lin_w, msg_w1, whh, wh_, wl_);
    wc_kernel<<<NLAYERS * 384, 128>>>(msg_w2, wih, msg_b2, wh_, wl_, bc);

    cudaMemsetAsync(deg, 0, NNODES * sizeof(float), 0);
    deg_kernel<<<(NEDGES + 255) / 256, 256>>>(ei, deg);

    const int gx = (NNODES + 63) / 64;

    // h = relu(x @ lin_w + lin_b)
    {
        dim3 grid(gx, 1);
        mma_gemm<<<grid, 256, MG_SMEM>>>(x, wh_, wl_, h, 128, nullptr, NNODES,
                                         lin_b, nullptr, nullptr, 1);
    }

    for (int l = 0; l < NLAYERS; ++l) {
        const float* W1e = msg_w1 + (size_t)l * 144 * 128 + 128 * 128;
        const int wbase = 128 + l * 512;
        const int cbase = 1664 + l * 384;

        // [t | gh] = h @ [w1h; whh]^T
        {
            dim3 grid(gx, 4);
            mma_gemm<<<grid, 256, MG_SMEM>>>(
                h, wh_ + (size_t)wbase * 128, wl_ + (size_t)wbase * 128,
                t, 128, gh, NNODES, msg_b1 + l * 128, bhh + l * 384, nullptr, 0);
        }
        cudaMemsetAsync(s, 0, (size_t)NNODES * HID * sizeof(float), 0);
        edge_mma_kernel<<<1536, 256, ET_SMEM>>>(ei, ea, t, s, W1e);
        // gi = s @ Wc + bih + deg*bc
        {
            dim3 grid(gx, 3);
            mma_gemm<<<grid, 256, MG_SMEM>>>(
                s, wh_ + (size_t)cbase * 128, wl_ + (size_t)cbase * 128,
                gi, 384, nullptr, NNODES, bih + l * 384, bc + l * 384, deg, 0);
        }
        gru_bn_kernel<<<(NNODES * 32 + 255) / 256, 256>>>(
            gi, gh, h, bn_g + l * 128, bn_b + l * 128, bn_m + l * 128, bn_v + l * 128);
    }

    offsets_kernel<<<2, 256>>>(batch, offs);
    readout_kernel<<<NGRAPHS, 128>>>(h, offs, z);
    ro_kernel<<<NGRAPHS, 128>>>(z, ro_w, ro_b, out);
}